// round 13
// baseline (speedup 1.0000x reference)
#include <cuda_runtime.h>
#include <cuda_fp16.h>
#include <cstdint>

#define Bq 4
#define Tq 12
#define Nq 4096
#define Fq 32

// ---------------------------------------------------------------------------
// PTX helpers — Ampere-era only (compute_103-safe: tcgen05 rejected by ptxas
// at the compute_103 virtual arch; s8 IMMA slow (R5); term-major order slow
// (R6); per-batch multi-stream graphs trip the upload-residue guard (R9)).
// ---------------------------------------------------------------------------
__device__ __forceinline__ uint32_t smem_to_u32(const void* p) {
    uint32_t a;
    asm("{ .reg .u64 t; cvta.to.shared.u64 t, %1; cvt.u32.u64 %0, t; }" : "=r"(a) : "l"(p));
    return a;
}

#define CP_ASYNC16(dst, src) \
    asm volatile("cp.async.cg.shared.global [%0], [%1], 16;" :: "r"(dst), "l"(src) : "memory")
#define CP_COMMIT() asm volatile("cp.async.commit_group;" ::: "memory")
#define CP_WAIT0()  asm volatile("cp.async.wait_group 0;" ::: "memory")
#define CP_WAIT1()  asm volatile("cp.async.wait_group 1;" ::: "memory")

__device__ __forceinline__ void ldsm4(uint32_t addr, uint32_t* r) {
    asm volatile("ldmatrix.sync.aligned.m8n8.x4.shared.b16 {%0,%1,%2,%3}, [%4];"
                 : "=r"(r[0]), "=r"(r[1]), "=r"(r[2]), "=r"(r[3]) : "r"(addr));
}
__device__ __forceinline__ void mma_f16(float* d, const uint32_t* a, uint32_t b0, uint32_t b1) {
    asm volatile("mma.sync.aligned.m16n8k16.row.col.f32.f16.f16.f32 "
                 "{%0,%1,%2,%3},{%4,%5,%6,%7},{%8,%9},{%0,%1,%2,%3};"
                 : "+f"(d[0]), "+f"(d[1]), "+f"(d[2]), "+f"(d[3])
                 : "r"(a[0]), "r"(a[1]), "r"(a[2]), "r"(a[3]), "r"(b0), "r"(b1));
}

// ---------------------------------------------------------------------------
// Device scratch (single fp16 operands — R11 error model)
// ---------------------------------------------------------------------------
__device__ __align__(128) __half g_Ah[(size_t)Bq * Nq * Nq];
__device__ __align__(128) __half g_xt[(size_t)Bq * Tq * Fq * Nq];   // [b][t*32+f][n]
__device__ __align__(128) __half g_St[(size_t)Bq * 2 * Fq * Nq];    // [b][64][n]  (h|m)
__device__ __align__(128) __half g_ht[(size_t)Bq * Fq * Nq];        // [b][32][n]  (h_mid)

__device__ __align__(128) float g_YX[(size_t)Bq * Tq * Nq * Fq];
__device__ __align__(128) float g_Y1[4 * (size_t)Bq * Nq * 2 * Fq]; // split-K=4 partials
__device__ __align__(128) float g_Y2[4 * (size_t)Bq * Nq * Fq];
__device__ __align__(128) float g_m [(size_t)Bq * Nq * Fq];
__device__ __align__(128) float g_c [(size_t)Bq * Nq * Fq];

__device__ __forceinline__ float sigf(float x) { return 1.0f / (1.0f + __expf(-x)); }

// ---------------------------------------------------------------------------
// adj -> fp16
// ---------------------------------------------------------------------------
__global__ __launch_bounds__(256) void convert_adj(const float* __restrict__ adj) {
    size_t i = (size_t)blockIdx.x * 256 + threadIdx.x;
    float4 v = ((const float4*)adj)[i];
    __half2 p0 = __floats2half2_rn(v.x, v.y);
    __half2 p1 = __floats2half2_rn(v.z, v.w);
    uint2 w;
    w.x = *(uint32_t*)&p0; w.y = *(uint32_t*)&p1;
    ((uint2*)g_Ah)[i] = w;
}

__global__ void init_state() {
    int i = blockIdx.x * blockDim.x + threadIdx.x;
    if (i < Bq * Nq * Fq) { g_m[i] = 1.0f; g_c[i] = 1.0f; }
    if (i < Bq * 2 * Fq * Nq) g_St[i] = __float2half(1.0f);
}

// ---------------------------------------------------------------------------
// transpose x: [z][4096][32] fp32 -> [z][32][4096] fp16
// ---------------------------------------------------------------------------
__global__ __launch_bounds__(256) void trans_x(const float* __restrict__ V,
                                               __half* __restrict__ T) {
    __shared__ float tile[64][33];
    const int z = blockIdx.z;
    const int n0 = blockIdx.x * 64;
    const float* v = V + (size_t)z * Nq * 32 + (size_t)n0 * 32;
    const int tid = threadIdx.x;
#pragma unroll
    for (int idx = tid; idx < 64 * 32; idx += 256)
        tile[idx >> 5][idx & 31] = v[idx];
    __syncthreads();
    __half* t = T + (size_t)z * 32 * Nq;
#pragma unroll
    for (int idx = tid; idx < 64 * 32; idx += 256) {
        int f = idx >> 6, j = idx & 63;
        t[(size_t)f * Nq + n0 + j] = __float2half(tile[j][f]);
    }
}

// ---------------------------------------------------------------------------
// fp16 mma.sync GEMM, superchunk K=64 per barrier (R12), zbase selects the
// absolute batch:  z = zbase + blockIdx.z.
//   Y[part=blockIdx.y][z] = adj[z][kseg] @ V[z][kseg]
// BM=128, 8 warps 4(m) x 2(n), fp32 accumulators, 2 CTAs/SM.
// ---------------------------------------------------------------------------
template <int BN>
__global__ __launch_bounds__(256, 2) void adj_gemm_mma(
    const __half* __restrict__ B_g,
    long long bZ, float* __restrict__ Y, long long yZ,
    int rstride, long long gstride, long long partStride, int nss, int zbase) {
    constexpr int RB = 80;                 // 64B data + 16B pad
    constexpr int A_BYTES = 128 * RB;      // 10240
    constexpr int B_BYTES = BN * RB;
    constexpr int OFF_B = A_BYTES;
    constexpr int SUB   = A_BYTES + B_BYTES;   // one 32-k sub-chunk
    constexpr int STAGE = 2 * SUB;             // superchunk (K=64)
    constexpr int WN = BN / 2;
    constexpr int NF = WN / 8;
    constexpr int NB = (NF + 1) / 2;

    extern __shared__ char smc[];
    const uint32_t sbase = smem_to_u32(smc);
    const int tid = threadIdx.x;
    const int wid = tid >> 5, lane = tid & 31;
    const int wm = wid & 3, wn = wid >> 2;
    const int z = zbase + blockIdx.z;
    const int m0 = blockIdx.x * 128;
    const int kbase = blockIdx.y * nss * 64;

    const __half* gA = g_Ah + (size_t)z * Nq * Nq + (size_t)m0 * Nq + kbase;
    const __half* gB = B_g + (size_t)z * bZ + kbase;

    const int arow = tid >> 2;             // 0..63, +64 for rep 1
    const int acol = tid & 3;
    const int brow = (BN == 64) ? (tid >> 2) : ((tid & 127) >> 2);
    const bool bact = (BN == 64) || (tid < 128);

    float acc[2][NF][4];
#pragma unroll
    for (int mf = 0; mf < 2; mf++)
#pragma unroll
        for (int nf = 0; nf < NF; nf++)
#pragma unroll
            for (int q = 0; q < 4; q++) acc[mf][nf][q] = 0.0f;

    auto issue = [&](int s) {
        const uint32_t st = sbase + (uint32_t)(s % 3) * STAGE;
#pragma unroll
        for (int kc = 0; kc < 2; kc++) {
            const uint32_t sb = st + kc * SUB;
            const int k0 = s * 64 + kc * 32;
#pragma unroll
            for (int rep = 0; rep < 2; rep++) {
                int r = rep * 64 + arow;
                CP_ASYNC16(sb + r * RB + acol * 16, gA + (size_t)r * Nq + k0 + acol * 8);
            }
            if (bact)
                CP_ASYNC16(sb + OFF_B + brow * RB + acol * 16,
                           gB + (size_t)brow * Nq + k0 + acol * 8);
        }
    };

    issue(0); CP_COMMIT();
    issue(1); CP_COMMIT();

    const int a_r = (lane & 15);
    const int a_k = (lane >> 4) * 16;
    const int b_r = ((lane >> 4) << 3) + (lane & 7);
    const int b_k = ((lane >> 3) & 1) * 16;

#pragma unroll 1
    for (int s = 0; s < nss; s++) {
        if (s + 1 < nss) { CP_WAIT1(); } else { CP_WAIT0(); }
        __syncthreads();
        if (s + 2 < nss) { issue(s + 2); CP_COMMIT(); }

        const uint32_t st = sbase + (uint32_t)(s % 3) * STAGE;
#pragma unroll
        for (int kc = 0; kc < 2; kc++) {
            const uint32_t sb = st + kc * SUB;
#pragma unroll
            for (int ks = 0; ks < 2; ks++) {
                uint32_t ah[2][4];
#pragma unroll
                for (int mf = 0; mf < 2; mf++) {
                    uint32_t addr = sb + (wm * 32 + mf * 16 + a_r) * RB + ks * 32 + a_k;
                    ldsm4(addr, ah[mf]);
                }
                uint32_t bh[NB][4];
#pragma unroll
                for (int nb = 0; nb < NB; nb++) {
                    uint32_t addr = sb + OFF_B + (wn * WN + nb * 16 + b_r) * RB + ks * 32 + b_k;
                    ldsm4(addr, bh[nb]);
                }
#pragma unroll
                for (int mf = 0; mf < 2; mf++)
#pragma unroll
                    for (int nf = 0; nf < NF; nf++) {
                        const int nb = nf >> 1, pr = (nf & 1) * 2;
                        mma_f16(acc[mf][nf], ah[mf], bh[nb][pr], bh[nb][pr + 1]);
                    }
            }
        }
    }

    float* yb = Y + (size_t)blockIdx.y * partStride + (size_t)z * yZ;
#pragma unroll
    for (int mf = 0; mf < 2; mf++)
#pragma unroll
        for (int nf = 0; nf < NF; nf++) {
            int r = m0 + wm * 32 + mf * 16 + (lane >> 2);
            int cj = wn * WN + nf * 8 + (lane & 3) * 2;
            size_t off = (size_t)(cj >> 5) * gstride + (cj & 31);
            float* o0 = yb + (size_t)r * rstride + off;
            float* o1 = yb + (size_t)(r + 8) * rstride + off;
            *(float2*)o0 = make_float2(acc[mf][nf][0], acc[mf][nf][1]);
            *(float2*)o1 = make_float2(acc[mf][nf][2], acc[mf][nf][3]);
        }
}

// ---------------------------------------------------------------------------
// gates1: LSTM gates 0..7 for a BATCH PAIR (bbase..bbase+1), row-blocked;
// sums 4 split-K partials; writes h_mid transposed fp16.
// grid 256: 256*8*4 = 8192 rows = exactly one sweep.
// ---------------------------------------------------------------------------
__global__ __launch_bounds__(256) void gates1_kernel(const float* __restrict__ W,
                                                     const float* __restrict__ bias,
                                                     int t, int bbase,
                                                     float* __restrict__ last_c) {
    extern __shared__ float sm[];
    float4* Wp = (float4*)sm;
    float4* bp = (float4*)(sm + 16384);
    const long long PS1 = (long long)Bq * Nq * 64;

    const int tid = threadIdx.x;
    for (int idx = tid; idx < 4096; idx += 256) {
        int l = idx & 31, p = (idx >> 5) & 3, k = idx >> 7;
        const float* W0 = W + (2 * p) * (Fq * 2 * Fq) + k * (2 * Fq);
        const float* W1 = W + (2 * p + 1) * (Fq * 2 * Fq) + k * (2 * Fq);
        Wp[idx] = make_float4(W0[l], W0[l + 32], W1[l], W1[l + 32]);
    }
    if (tid < 128) {
        int l = tid & 31, p = tid >> 5;
        bp[p * 32 + l] = make_float4(bias[(2 * p) * 64 + l], bias[(2 * p) * 64 + 32 + l],
                                     bias[(2 * p + 1) * 64 + l], bias[(2 * p + 1) * 64 + 32 + l]);
    }
    __syncthreads();

    const int w = tid >> 5, l = tid & 31;
    const int nlocal = 2 * Nq;
#pragma unroll 1
    for (int lr0 = blockIdx.x * 32 + w * 4; lr0 < nlocal; lr0 += gridDim.x * 32) {
        float yx[4], yh[4];
#pragma unroll
        for (int i = 0; i < 4; i++) {
            int row = bbase * Nq + lr0 + i;
            int b = row >> 12, n = row & (Nq - 1);
            yx[i] = g_YX[(((size_t)b * Tq + t) * Nq + n) * Fq + l];
            float s = 0.f;
#pragma unroll
            for (int p = 0; p < 4; p++) s += g_Y1[p * PS1 + (size_t)row * 64 + l];
            yh[i] = s;
        }

        float acc[4][4][4];
#pragma unroll
        for (int i = 0; i < 4; i++)
#pragma unroll
            for (int p = 0; p < 4; p++)
#pragma unroll
                for (int q = 0; q < 4; q++) acc[i][p][q] = 0.0f;

#pragma unroll
        for (int k = 0; k < 32; k++) {
            float ykx[4], ykh[4];
#pragma unroll
            for (int i = 0; i < 4; i++) {
                ykx[i] = __shfl_sync(0xffffffffu, yx[i], k);
                ykh[i] = __shfl_sync(0xffffffffu, yh[i], k);
            }
#pragma unroll
            for (int p = 0; p < 4; p++) {
                float4 wv = Wp[k * 128 + p * 32 + l];
#pragma unroll
                for (int i = 0; i < 4; i++) {
                    acc[i][p][0] = fmaf(ykx[i], wv.x, acc[i][p][0]);
                    acc[i][p][1] = fmaf(ykx[i], wv.y, acc[i][p][1]);
                    acc[i][p][2] = fmaf(ykh[i], wv.z, acc[i][p][2]);
                    acc[i][p][3] = fmaf(ykh[i], wv.w, acc[i][p][3]);
                }
            }
        }

#pragma unroll
        for (int i = 0; i < 4; i++) {
            int row = bbase * Nq + lr0 + i;
            int b = row >> 12, n = row & (Nq - 1);
            float s[4];
#pragma unroll
            for (int p = 0; p < 4; p++) {
                float4 bb = bp[p * 32 + l];
                float gx = (acc[i][p][0] + bb.x) * sigf(acc[i][p][1] + bb.y);
                float gh = (acc[i][p][2] + bb.z) * sigf(acc[i][p][3] + bb.w);
                s[p] = gx + gh;
            }
            float f  = sigf(s[0]);
            float ig = sigf(s[1]);
            float o  = sigf(s[3]);
            size_t ci = (size_t)row * Fq + l;
            float cn = f * g_c[ci] + ig * tanhf(s[2]);
            g_c[ci] = cn;
            float hm = o * tanhf(cn);
            g_ht[((size_t)b * Fq + l) * Nq + n] = __float2half(hm);
            if (t == Tq - 1) last_c[ci] = cn;
        }
    }
}

// ---------------------------------------------------------------------------
// gates2: memory gates 8..13 for a BATCH PAIR, row-blocked; sums 4 split-K
// partials; writes new [h|m] transposed fp16.
// ---------------------------------------------------------------------------
__global__ __launch_bounds__(256) void gates2_kernel(const float* __restrict__ W8,
                                                     const float* __restrict__ bias8,
                                                     int t, int bbase,
                                                     float* __restrict__ hidden,
                                                     float* __restrict__ last_h,
                                                     float* __restrict__ last_m) {
    extern __shared__ float sm[];
    float4* Wp = (float4*)sm;
    float4* bp = (float4*)(sm + 12288);
    const long long PS1 = (long long)Bq * Nq * 64;
    const long long PS2 = (long long)Bq * Nq * 32;

    const int tid = threadIdx.x;
    for (int idx = tid; idx < 3072; idx += 256) {
        int k = idx / 96, r = idx % 96, p = r >> 5, l = r & 31;
        const float* W0 = W8 + (2 * p) * (Fq * 2 * Fq) + k * (2 * Fq);
        const float* W1 = W8 + (2 * p + 1) * (Fq * 2 * Fq) + k * (2 * Fq);
        Wp[idx] = make_float4(W0[l], W0[l + 32], W1[l], W1[l + 32]);
    }
    if (tid < 96) {
        int p = tid >> 5, l = tid & 31;
        bp[tid] = make_float4(bias8[(2 * p) * 64 + l], bias8[(2 * p) * 64 + 32 + l],
                              bias8[(2 * p + 1) * 64 + l], bias8[(2 * p + 1) * 64 + 32 + l]);
    }
    __syncthreads();

    const int w = tid >> 5, l = tid & 31;
    const int nlocal = 2 * Nq;
#pragma unroll 1
    for (int lr0 = blockIdx.x * 32 + w * 4; lr0 < nlocal; lr0 += gridDim.x * 32) {
        float y2[4], ym[4];
#pragma unroll
        for (int i = 0; i < 4; i++) {
            int row = bbase * Nq + lr0 + i;
            float a2 = 0.f, am = 0.f;
#pragma unroll
            for (int p = 0; p < 4; p++) {
                a2 += g_Y2[p * PS2 + (size_t)row * 32 + l];
                am += g_Y1[p * PS1 + (size_t)row * 64 + 32 + l];
            }
            y2[i] = a2; ym[i] = am;
        }

        float acc[4][3][4];
#pragma unroll
        for (int i = 0; i < 4; i++)
#pragma unroll
            for (int p = 0; p < 3; p++)
#pragma unroll
                for (int q = 0; q < 4; q++) acc[i][p][q] = 0.0f;

#pragma unroll
        for (int k = 0; k < 32; k++) {
            float yk2[4], ykm[4];
#pragma unroll
            for (int i = 0; i < 4; i++) {
                yk2[i] = __shfl_sync(0xffffffffu, y2[i], k);
                ykm[i] = __shfl_sync(0xffffffffu, ym[i], k);
            }
#pragma unroll
            for (int p = 0; p < 3; p++) {
                float4 wv = Wp[k * 96 + p * 32 + l];
#pragma unroll
                for (int i = 0; i < 4; i++) {
                    acc[i][p][0] = fmaf(yk2[i], wv.x, acc[i][p][0]);
                    acc[i][p][1] = fmaf(yk2[i], wv.y, acc[i][p][1]);
                    acc[i][p][2] = fmaf(ykm[i], wv.z, acc[i][p][2]);
                    acc[i][p][3] = fmaf(ykm[i], wv.w, acc[i][p][3]);
                }
            }
        }

#pragma unroll
        for (int i = 0; i < 4; i++) {
            int row = bbase * Nq + lr0 + i;
            int b = row >> 12, n = row & (Nq - 1);
            float s[3];
#pragma unroll
            for (int p = 0; p < 3; p++) {
                float4 bb = bp[p * 32 + l];
                float gx = (acc[i][p][0] + bb.x) * sigf(acc[i][p][1] + bb.y);
                float gh = (acc[i][p][2] + bb.z) * sigf(acc[i][p][3] + bb.w);
                s[p] = gx + gh;
            }
            float i2 = sigf(s[0]);
            float gg = sigf(s[1]);
            float o2 = sigf(s[2]);
            size_t ci = (size_t)row * Fq + l;
            float mo = g_m[ci];
            float mn = i2 * mo + (1.0f - i2) * gg;
            float hn = mn * o2;
            g_m[ci] = mn;
            g_St[((size_t)b * 64 + l) * Nq + n]      = __float2half(hn);
            g_St[((size_t)b * 64 + 32 + l) * Nq + n] = __float2half(mn);
            hidden[(((size_t)b * Tq + t) * Nq + n) * Fq + l] = hn;
            if (t == Tq - 1) {
                last_h[ci] = hn;
                last_m[ci] = mn;
            }
        }
    }
}

// ---------------------------------------------------------------------------
// kernel_launch — BATCH-PAIR CHAINING: run batches {0,1} through all 12
// steps, then {2,3}. Per-pair fp16 adj = 67 MB < L2 (126 MB), so every
// recurrent pass after the first re-reads adj from L2 instead of HBM.
// Precompute on one side stream (R8-proven pattern), pieces for the first
// pair's batches scheduled first.
// ---------------------------------------------------------------------------
extern "C" void kernel_launch(void* const* d_in, const int* in_sizes, int n_in,
                              void* d_out, int out_size) {
    (void)in_sizes; (void)n_in; (void)out_size;
    const float* x    = (const float*)d_in[0];
    const float* adj  = (const float*)d_in[1];
    const float* W    = (const float*)d_in[2];
    const float* bias = (const float*)d_in[3];

    float* hidden = (float*)d_out;
    float* last_h = hidden + (size_t)Bq * Tq * Nq * Fq;
    float* last_c = last_h + (size_t)Bq * Nq * Fq;
    float* last_m = last_c + (size_t)Bq * Nq * Fq;

    float *pYX, *pY1, *pY2;
    __half *pxt, *pSt, *pht;
    cudaGetSymbolAddress((void**)&pYX, g_YX);
    cudaGetSymbolAddress((void**)&pY1, g_Y1);
    cudaGetSymbolAddress((void**)&pY2, g_Y2);
    cudaGetSymbolAddress((void**)&pxt, g_xt);
    cudaGetSymbolAddress((void**)&pSt, g_St);
    cudaGetSymbolAddress((void**)&pht, g_ht);

    const int G1_SMEM = (16384 + 512) * 4;
    const int G2_SMEM = (12288 + 384) * 4;
    const int GEMM64_SMEM = 3 * 2 * (128 * 80 + 64 * 80);  // 92160
    const int GEMM32_SMEM = 3 * 2 * (128 * 80 + 32 * 80);  // 76800

    static bool inited = false;
    static cudaStream_t s2;
    static cudaEvent_t evFork, evPre[12];
    if (!inited) {
        cudaFuncSetAttribute(gates1_kernel, cudaFuncAttributeMaxDynamicSharedMemorySize, G1_SMEM);
        cudaFuncSetAttribute(gates2_kernel, cudaFuncAttributeMaxDynamicSharedMemorySize, G2_SMEM);
        cudaFuncSetAttribute((void*)adj_gemm_mma<64>,
                             cudaFuncAttributeMaxDynamicSharedMemorySize, GEMM64_SMEM);
        cudaFuncSetAttribute((void*)adj_gemm_mma<32>,
                             cudaFuncAttributeMaxDynamicSharedMemorySize, GEMM32_SMEM);
        cudaStreamCreateWithFlags(&s2, cudaStreamNonBlocking);
        cudaEventCreateWithFlags(&evFork, cudaEventDisableTiming);
        for (int p = 0; p < 12; p++)
            cudaEventCreateWithFlags(&evPre[p], cudaEventDisableTiming);
        inited = true;
    }

    cudaStream_t s0 = 0;

    convert_adj<<<(Bq * Nq * Nq / 4) / 256, 256, 0, s0>>>(adj);
    init_state<<<(Bq * 2 * Fq * Nq + 255) / 256, 256, 0, s0>>>();
    trans_x<<<dim3(Nq / 64, 1, Bq * Tq), 256, 0, s0>>>(x, pxt);

    // Fork: precompute adj @ x on side stream. 12 pieces: (batch-pair, t-pair),
    // first chain's batches first.
    cudaEventRecord(evFork, s0);
    cudaStreamWaitEvent(s2, evFork, 0);
    for (int c = 0; c < 2; c++) {
        for (int tp = 0; tp < 6; tp++) {
            adj_gemm_mma<64><<<dim3(Nq / 128, 1, 2), 256, GEMM64_SMEM, s2>>>(
                pxt + (size_t)tp * 64 * Nq,
                (long long)Tq * Fq * Nq,
                pYX + (size_t)tp * 2 * Nq * Fq, (long long)Tq * Nq * Fq,
                32, (long long)Nq * 32, 0LL, Nq / 64, c * 2);
            cudaEventRecord(evPre[c * 6 + tp], s2);
        }
    }

    const long long PS1 = (long long)Bq * Nq * 64;
    const long long PS2 = (long long)Bq * Nq * 32;
    for (int c = 0; c < 2; c++) {
        const int zb = c * 2;
        for (int t = 0; t < Tq; t++) {
            // Y1 = adj @ [h|m]^T   (batch pair, split-K=4: 256 CTAs = 1 wave)
            adj_gemm_mma<64><<<dim3(Nq / 128, 4, 2), 256, GEMM64_SMEM, s0>>>(
                pSt, (long long)64 * Nq, pY1, (long long)Nq * 64,
                64, 32LL, PS1, Nq / 256, zb);
            if ((t & 1) == 0) cudaStreamWaitEvent(s0, evPre[c * 6 + (t >> 1)], 0);
            gates1_kernel<<<256, 256, G1_SMEM, s0>>>(W, bias, t, zb, last_c);
            // Y2 = adj @ h_mid^T   (batch pair, split-K=4)
            adj_gemm_mma<32><<<dim3(Nq / 128, 4, 2), 256, GEMM32_SMEM, s0>>>(
                pht, (long long)32 * Nq, pY2, (long long)Nq * 32,
                32, 32LL, PS2, Nq / 256, zb);
            gates2_kernel<<<256, 256, G2_SMEM, s0>>>(W + 8 * (Fq * 2 * Fq),
                                                     bias + 8 * (2 * Fq),
                                                     t, zb, hidden, last_h, last_m);
        }
    }
}